// round 10
// baseline (speedup 1.0000x reference)
#include <cuda_runtime.h>

#define TT   1024
#define BB   16
#define CC   1024
#define HH   16
#define KW   7
#define PADL 6
#define MM   (TT * BB)       // 16384
#define NN   (HH * KW)       // 112
#define KD   1024

#define BM 128
#define BK 32
#define NTILE (KD / BK)                             // 32
#define GEMM_BLOCKS (MM / BM)                       // 128
#define DENSE_BYTES ((size_t)BB * HH * TT * TT * 4) // 1 GiB

#define ASTR 130      // floats per p-row of A tile (8B-aligned 4ty offsets)
#define BSTR 33       // ulls per o-row of B tile (conflict-free LDS64)

// softmaxed conv weights, [m = t*16+b][o = h*7+k]
__device__ float g_wsm[(size_t)MM * NN];

typedef unsigned long long ull;
__device__ __forceinline__ ull pk2(float lo, float hi) {
    ull r; asm("mov.b64 %0,{%1,%2};" : "=l"(r) : "f"(lo), "f"(hi)); return r;
}
__device__ __forceinline__ void upk2(ull v, float& lo, float& hi) {
    asm("mov.b64 {%0,%1},%2;" : "=f"(lo), "=f"(hi) : "l"(v));
}
__device__ __forceinline__ void fma2(ull& d, ull a, ull b) {
    asm("fma.rn.f32x2 %0,%1,%2,%3;" : "=l"(d) : "l"(a), "l"(b), "l"(d));
}

// ---------------------------------------------------------------------------
// GEMM  w = x @ W^T (16384 x 112 x 1024) + masked softmax over K=7 -> g_wsm
// 512 threads (16 warps/SM = 4/SMSP), 4 rows/thread, software-pipelined.
// ---------------------------------------------------------------------------
__global__ __launch_bounds__(512)
void k_gemm_softmax(const float* __restrict__ x,
                    const float* __restrict__ W)
{
    __shared__ __align__(16) float Asf[BK * ASTR];   // 16640 B
    __shared__ __align__(16) ull   Bsd[NN * BSTR];   // 29568 B

    const int tid   = threadIdx.x;
    const int tx    = tid & 15;      // head
    const int ty    = tid >> 4;      // 0..31, rows 4ty..4ty+3
    const int mBase = blockIdx.x * BM;

    const int kk  = tid & 31;        // loader column
    const int ldr = tid >> 5;        // loader row phase 0..15

    const float* pa = x + (size_t)(mBase + ldr) * KD + kk;
    const float* pb = W + (size_t)ldr * KD + kk;

    ull acc[7][2];
#pragma unroll
    for (int j = 0; j < 7; j++) { acc[j][0] = 0ull; acc[j][1] = 0ull; }

    float aReg[8], bReg[7];

    // prologue: tile 0
#pragma unroll
    for (int rr = 0; rr < 8; rr++) aReg[rr] = pa[rr * 16 * KD];
#pragma unroll
    for (int oo = 0; oo < 7; oo++) bReg[oo] = pb[oo * 16 * KD];
#pragma unroll
    for (int rr = 0; rr < 8; rr++) Asf[kk * ASTR + ldr + rr * 16] = aReg[rr];
#pragma unroll
    for (int oo = 0; oo < 7; oo++) Bsd[(ldr + oo * 16) * BSTR + kk] = pk2(bReg[oo], bReg[oo]);
    __syncthreads();

    for (int kt = 1; kt <= NTILE; kt++) {
        const int k0 = kt * BK;
        if (kt < NTILE) {
            // next tile's LDGs land during compute
#pragma unroll
            for (int rr = 0; rr < 8; rr++) aReg[rr] = pa[rr * 16 * KD + k0];
#pragma unroll
            for (int oo = 0; oo < 7; oo++) bReg[oo] = pb[oo * 16 * KD + k0];
        }

#pragma unroll 4
        for (int p = 0; p < BK; p++) {
            const float* ap = &Asf[p * ASTR + 4 * ty];
            ull a01 = *(const ull*)(ap + 0);     // rows (4ty, 4ty+1) packed
            ull a23 = *(const ull*)(ap + 2);     // rows (4ty+2, 4ty+3)
#pragma unroll
            for (int j = 0; j < 7; j++) {
                ull bb = Bsd[(tx * 7 + j) * BSTR + p];
                fma2(acc[j][0], a01, bb);
                fma2(acc[j][1], a23, bb);
            }
        }
        __syncthreads();

        if (kt < NTILE) {
#pragma unroll
            for (int rr = 0; rr < 8; rr++) Asf[kk * ASTR + ldr + rr * 16] = aReg[rr];
#pragma unroll
            for (int oo = 0; oo < 7; oo++) Bsd[(ldr + oo * 16) * BSTR + kk] = pk2(bReg[oo], bReg[oo]);
            __syncthreads();
        }
    }

    // masked softmax over K=7 for this thread's 4 rows, head tx
#pragma unroll
    for (int rp = 0; rp < 2; rp++) {
        float f0[7], f1[7];
#pragma unroll
        for (int j = 0; j < 7; j++) upk2(acc[j][rp], f0[j], f1[j]);

#pragma unroll
        for (int half = 0; half < 2; half++) {
            float* f = half ? f1 : f0;
            int m = mBase + ty * 4 + rp * 2 + half;
            int t = m >> 4;
            int kmin = PADL - t; if (kmin < 0) kmin = 0;

            float mx = -1e30f;
#pragma unroll
            for (int k = 0; k < 7; k++)
                if (k >= kmin && f[k] > mx) mx = f[k];

            float e[7], s = 0.f;
#pragma unroll
            for (int k = 0; k < 7; k++) {
                e[k] = (k >= kmin) ? __expf(f[k] - mx) : 0.f;
                s += e[k];
            }
            float inv = 1.f / s;
            float* gp = &g_wsm[(size_t)m * NN + tx * 7];
#pragma unroll
            for (int k = 0; k < 7; k++)
                gp[k] = e[k] * inv;
        }
    }
}

// ---------------------------------------------------------------------------
// k_out: eight consecutive t per block; 14 gather loads feed 8 outputs.
//   out[t,b,:] = sum_k wsm[t,b,h,k] * x[clamp(t-6+k), b, :]
// ---------------------------------------------------------------------------
__global__ __launch_bounds__(256)
void k_out(const float* __restrict__ x,
           float* __restrict__ out)
{
    const int t0  = blockIdx.x * 8;
    const int b   = blockIdx.y;
    const int tid = threadIdx.x;

    __shared__ float sw[8 * NN];
    for (int e = tid; e < 8 * NN; e += 256) {
        int r = e / NN, idx = e - r * NN;
        sw[e] = g_wsm[(size_t)((t0 + r) * BB + b) * NN + idx];
    }
    __syncthreads();

    const int h = tid >> 4;
    const float4* x4 = (const float4*)x;

    float4 v[14];
#pragma unroll
    for (int k = 0; k < 14; k++) {
        int pos = t0 - PADL + k;
        if (pos < 0) pos = 0;               // weight is exactly 0 there
        v[k] = x4[((size_t)(pos * BB + b) << 8) + tid];
    }

    float4* out4 = (float4*)out;
#pragma unroll
    for (int r = 0; r < 8; r++) {
        const float* wr = &sw[r * NN + h * 7];
        float4 a = make_float4(0.f, 0.f, 0.f, 0.f);
#pragma unroll
        for (int k = 0; k < 7; k++) {
            float wk = wr[k];
            a.x += wk * v[r + k].x;
            a.y += wk * v[r + k].y;
            a.z += wk * v[r + k].z;
            a.w += wk * v[r + k].w;
        }
        out4[((size_t)((t0 + r) * BB + b) << 8) + tid] = a;
    }
}

// ---------------------------------------------------------------------------
// k_band: one element per thread; coalesced g_wsm read, one scattered STG.
// ---------------------------------------------------------------------------
__global__ __launch_bounds__(256)
void k_band(float* __restrict__ dense)
{
    int gt  = blockIdx.x * 256 + threadIdx.x;   // 0 .. MM*NN-1
    int m   = gt / NN;
    int idx = gt - m * NN;
    int t   = m >> 4;
    int b   = m & 15;
    int h   = idx / 7;
    int k   = idx - h * 7;
    int col = t - PADL + k;
    if (col >= 0)
        dense[((size_t)(b * HH + h) << 20) + ((size_t)t << 10) + col] = g_wsm[gt];
}

// ---------------------------------------------------------------------------
// Serial: gemm -> memset(dense) -> k_out -> k_band.
// ---------------------------------------------------------------------------
extern "C" void kernel_launch(void* const* d_in, const int* in_sizes, int n_in,
                              void* d_out, int out_size)
{
    const float* x = (const float*)d_in[0];   // (T, B, C) fp32
    const float* W = (const float*)d_in[1];   // (H*K, C)  fp32
    float* out   = (float*)d_out;
    float* dense = out + (size_t)MM * CC;

    k_gemm_softmax<<<GEMM_BLOCKS, 512>>>(x, W);
    cudaMemsetAsync(dense, 0, DENSE_BYTES);
    dim3 g2(TT / 8, BB);
    k_out<<<g2, 256>>>(x, out);
    k_band<<<(MM * NN) / 256, 256>>>(dense);
}

// round 11
// speedup vs baseline: 1.1047x; 1.1047x over previous
#include <cuda_runtime.h>

#define TT   1024
#define BB   16
#define CC   1024
#define HH   16
#define KW   7
#define PADL 6
#define MM   (TT * BB)       // 16384
#define NN   (HH * KW)       // 112
#define KD   1024

#define BM 128
#define BK 32
#define NTILE (KD / BK)                             // 32
#define GEMM_BLOCKS (MM / BM)                       // 128
#define DENSE_BYTES ((size_t)BB * HH * TT * TT * 4) // 1 GiB

#define ASTR 130      // floats per p-row of A tile
#define BSTR 33       // ulls per o-row of B tile (14*tx mod 32: conflict-free)

// softmaxed conv weights, [m = t*16+b][o = h*7+k]
__device__ float g_wsm[(size_t)MM * NN];

typedef unsigned long long ull;
__device__ __forceinline__ ull pk2(float lo, float hi) {
    ull r; asm("mov.b64 %0,{%1,%2};" : "=l"(r) : "f"(lo), "f"(hi)); return r;
}
__device__ __forceinline__ void upk2(ull v, float& lo, float& hi) {
    asm("mov.b64 {%0,%1},%2;" : "=f"(lo), "=f"(hi) : "l"(v));
}
__device__ __forceinline__ void fma2(ull& d, ull a, ull b) {
    asm("fma.rn.f32x2 %0,%1,%2,%3;" : "=l"(d) : "l"(a), "l"(b), "l"(d));
}
__device__ __forceinline__ ull add2(ull a, ull b) {
    ull r; asm("add.rn.f32x2 %0,%1,%2;" : "=l"(r) : "l"(a), "l"(b)); return r;
}

// ---------------------------------------------------------------------------
// GEMM  w = x @ W^T (16384 x 112 x 1024) + masked softmax over K=7 -> g_wsm
// 512 threads, BM=128, 8 rows/thread, SPLIT-K inside the block:
//   tid <  256 : p = 0..15 of each tile
//   tid >= 256 : p = 16..31
// End: one cross-half reduction through smem. LDS ratio of the 8-row config,
// latency cover of 16 warps/SM.
// ---------------------------------------------------------------------------
__global__ __launch_bounds__(512)
void k_gemm_softmax(const float* __restrict__ x,
                    const float* __restrict__ W)
{
    __shared__ __align__(16) float Asf[BK * ASTR];   // 16640 B, [p][m]
    __shared__ __align__(16) ull   Bsd[NN * BSTR];   // 29568 B, [o][p] dup'd

    const int tid   = threadIdx.x;
    const int htid  = tid & 255;
    const int tx    = htid & 15;    // head
    const int ty    = htid >> 4;    // 0..15, rows 8ty..8ty+7
    const int ph    = tid >> 8;     // p-half: 0 or 1
    const int p0    = ph * 16;
    const int mBase = blockIdx.x * BM;

    const int kk  = tid & 31;       // loader column
    const int ldr = tid >> 5;       // loader row phase 0..15

    const float* pa = x + (size_t)(mBase + ldr) * KD + kk;
    const float* pb = W + (size_t)ldr * KD + kk;

    ull acc[7][4];
#pragma unroll
    for (int j = 0; j < 7; j++)
#pragma unroll
        for (int r = 0; r < 4; r++) acc[j][r] = 0ull;

    float aReg[8], bReg[7];

    // prologue: load tile 0 (512 threads: 8 A elems + 7 B elems each)
#pragma unroll
    for (int rr = 0; rr < 8; rr++) aReg[rr] = pa[rr * 16 * KD];
#pragma unroll
    for (int oo = 0; oo < 7; oo++) bReg[oo] = pb[oo * 16 * KD];
#pragma unroll
    for (int rr = 0; rr < 8; rr++) Asf[kk * ASTR + ldr + rr * 16] = aReg[rr];
#pragma unroll
    for (int oo = 0; oo < 7; oo++) Bsd[(ldr + oo * 16) * BSTR + kk] = pk2(bReg[oo], bReg[oo]);
    __syncthreads();

    for (int kt = 1; kt <= NTILE; kt++) {
        const int k0 = kt * BK;
        if (kt < NTILE) {
#pragma unroll
            for (int rr = 0; rr < 8; rr++) aReg[rr] = pa[rr * 16 * KD + k0];
#pragma unroll
            for (int oo = 0; oo < 7; oo++) bReg[oo] = pb[oo * 16 * KD + k0];
        }

#pragma unroll 4
        for (int pp = 0; pp < 16; pp++) {
            const int p = p0 + pp;
            const float* ap = &Asf[p * ASTR + 8 * ty];
            ull a0 = *(const ull*)(ap + 0);
            ull a1 = *(const ull*)(ap + 2);
            ull a2 = *(const ull*)(ap + 4);
            ull a3 = *(const ull*)(ap + 6);
#pragma unroll
            for (int j = 0; j < 7; j++) {
                ull bb = Bsd[(tx * 7 + j) * BSTR + p];
                fma2(acc[j][0], a0, bb);
                fma2(acc[j][1], a1, bb);
                fma2(acc[j][2], a2, bb);
                fma2(acc[j][3], a3, bb);
            }
        }
        __syncthreads();

        if (kt < NTILE) {
#pragma unroll
            for (int rr = 0; rr < 8; rr++) Asf[kk * ASTR + ldr + rr * 16] = aReg[rr];
#pragma unroll
            for (int oo = 0; oo < 7; oo++) Bsd[(ldr + oo * 16) * BSTR + kk] = pk2(bReg[oo], bReg[oo]);
            __syncthreads();
        }
    }

    // ---- cross-half reduction (two 28KB chunks through the Bsd region) ----
    ull* xch = Bsd;                                  // reuse B tile space
#pragma unroll
    for (int c = 0; c < 2; c++) {                    // chunk c: acc[.][2c..2c+1]
        if (ph == 1) {
#pragma unroll
            for (int j = 0; j < 7; j++) {
                xch[htid * 14 + j * 2 + 0] = acc[j][2 * c + 0];
                xch[htid * 14 + j * 2 + 1] = acc[j][2 * c + 1];
            }
        }
        __syncthreads();
        if (ph == 0) {
#pragma unroll
            for (int j = 0; j < 7; j++) {
                acc[j][2 * c + 0] = add2(acc[j][2 * c + 0], xch[htid * 14 + j * 2 + 0]);
                acc[j][2 * c + 1] = add2(acc[j][2 * c + 1], xch[htid * 14 + j * 2 + 1]);
            }
        }
        __syncthreads();
    }

    if (ph == 1) return;

    // ---- masked softmax over K=7 for this thread's 8 rows, head tx ----
#pragma unroll
    for (int rp = 0; rp < 4; rp++) {
        float f0[7], f1[7];
#pragma unroll
        for (int j = 0; j < 7; j++) upk2(acc[j][rp], f0[j], f1[j]);

#pragma unroll
        for (int half = 0; half < 2; half++) {
            float* f = half ? f1 : f0;
            int m = mBase + ty * 8 + rp * 2 + half;
            int t = m >> 4;
            int kmin = PADL - t; if (kmin < 0) kmin = 0;

            float mx = -1e30f;
#pragma unroll
            for (int k = 0; k < 7; k++)
                if (k >= kmin && f[k] > mx) mx = f[k];

            float e[7], s = 0.f;
#pragma unroll
            for (int k = 0; k < 7; k++) {
                e[k] = (k >= kmin) ? __expf(f[k] - mx) : 0.f;
                s += e[k];
            }
            float inv = 1.f / s;
            float* gp = &g_wsm[(size_t)m * NN + tx * 7];
#pragma unroll
            for (int k = 0; k < 7; k++)
                gp[k] = e[k] * inv;
        }
    }
}

// ---------------------------------------------------------------------------
// k_out: eight consecutive t per block; 14 gather loads feed 8 outputs.
// ---------------------------------------------------------------------------
__global__ __launch_bounds__(256)
void k_out(const float* __restrict__ x,
           float* __restrict__ out)
{
    const int t0  = blockIdx.x * 8;
    const int b   = blockIdx.y;
    const int tid = threadIdx.x;

    __shared__ float sw[8 * NN];
    for (int e = tid; e < 8 * NN; e += 256) {
        int r = e / NN, idx = e - r * NN;
        sw[e] = g_wsm[(size_t)((t0 + r) * BB + b) * NN + idx];
    }
    __syncthreads();

    const int h = tid >> 4;
    const float4* x4 = (const float4*)x;

    float4 v[14];
#pragma unroll
    for (int k = 0; k < 14; k++) {
        int pos = t0 - PADL + k;
        if (pos < 0) pos = 0;               // weight is exactly 0 there
        v[k] = x4[((size_t)(pos * BB + b) << 8) + tid];
    }

    float4* out4 = (float4*)out;
#pragma unroll
    for (int r = 0; r < 8; r++) {
        const float* wr = &sw[r * NN + h * 7];
        float4 a = make_float4(0.f, 0.f, 0.f, 0.f);
#pragma unroll
        for (int k = 0; k < 7; k++) {
            float wk = wr[k];
            a.x += wk * v[r + k].x;
            a.y += wk * v[r + k].y;
            a.z += wk * v[r + k].z;
            a.w += wk * v[r + k].w;
        }
        out4[((size_t)((t0 + r) * BB + b) << 8) + tid] = a;
    }
}

// ---------------------------------------------------------------------------
// k_band: one element per thread; coalesced g_wsm read, one scattered STG.
// ---------------------------------------------------------------------------
__global__ __launch_bounds__(256)
void k_band(float* __restrict__ dense)
{
    int gt  = blockIdx.x * 256 + threadIdx.x;   // 0 .. MM*NN-1
    int m   = gt / NN;
    int idx = gt - m * NN;
    int t   = m >> 4;
    int b   = m & 15;
    int h   = idx / 7;
    int k   = idx - h * 7;
    int col = t - PADL + k;
    if (col >= 0)
        dense[((size_t)(b * HH + h) << 20) + ((size_t)t << 10) + col] = g_wsm[gt];
}

// ---------------------------------------------------------------------------
// Serial: gemm -> memset(dense) -> k_out -> k_band.
// ---------------------------------------------------------------------------
extern "C" void kernel_launch(void* const* d_in, const int* in_sizes, int n_in,
                              void* d_out, int out_size)
{
    const float* x = (const float*)d_in[0];   // (T, B, C) fp32
    const float* W = (const float*)d_in[1];   // (H*K, C)  fp32
    float* out   = (float*)d_out;
    float* dense = out + (size_t)MM * CC;

    k_gemm_softmax<<<GEMM_BLOCKS, 512>>>(x, W);
    cudaMemsetAsync(dense, 0, DENSE_BYTES);
    dim3 g2(TT / 8, BB);
    k_out<<<g2, 256>>>(x, out);
    k_band<<<(MM * NN) / 256, 256>>>(dense);
}